// round 14
// baseline (speedup 1.0000x reference)
#include <cuda_runtime.h>
#include <cuda_fp16.h>
#include <cstdint>

// Problem dims
#define T_DIM 8192
#define K_DIM 4096
#define O_DIM 11008
#define QB    64

// Two-term split: A row = [xh(4096) | xl(4096)], B row = [wh(4096) | wl(4096)]
#define AK 8192

// tcgen05 GEMM tiling: 256x256 CTA tile (full 512 TMEM cols), K64 stage
#define BM 256
#define BN 256
#define BK 64
#define NSTAGE 3
#define KBLKS 192                   // 64 (xh*wh) + 64 (xh*wl) + 64 (xl*wh)
#define NTHREADS 512

#define A_ST_BYTES (BM * 128)       // 32768
#define B_ST_BYTES (BN * 128)       // 32768
#define STAGE_BYTES (A_ST_BYTES + B_ST_BYTES)  // 65536
#define SMEM_BARS  (NSTAGE * STAGE_BYTES)      // 196608
#define SMEM_TMEMP (SMEM_BARS + NSTAGE * 8)
#define SMEM_TOTAL (SMEM_TMEMP + 8)            // 196640

// HMMA fallback (never runs; compute_103 pass only) uses its own 48KB stages
#define FB_A_BYTES 16384
#define FB_STAGE   49152

// fp16 scratch (static device arrays: allocation-free contract)
__device__ __align__(16) __half g_a[(size_t)T_DIM * AK];   // [xh | xl]
__device__ __align__(16) __half g_b[(size_t)O_DIM * AK];   // [wh | wl]

// ---------------------------------------------------------------- helpers
__device__ __forceinline__ uint32_t smem_u32(const void* p) {
    uint32_t a;
    asm("{ .reg .u64 t; cvta.to.shared.u64 t, %1; cvt.u32.u64 %0, t; }" : "=r"(a) : "l"(p));
    return a;
}
__device__ __forceinline__ uint32_t swz(uint32_t off) { return off ^ ((off >> 3) & 0x70); }

__device__ __forceinline__ void cp_async16(uint32_t dst, const void* src) {
    asm volatile("cp.async.cg.shared.global [%0], [%1], 16;\n" :: "r"(dst), "l"(src));
}
__device__ __forceinline__ void cp_commit() { asm volatile("cp.async.commit_group;\n" ::: "memory"); }
template <int N>
__device__ __forceinline__ void cp_wait() { asm volatile("cp.async.wait_group %0;\n" :: "n"(N) : "memory"); }

// ---------------------------------------------------------------- prep kernels (proven)
__global__ void __launch_bounds__(256) xsplit_kernel(const float* __restrict__ x) {
    const size_t n4 = (size_t)T_DIM * K_DIM / 4;
    for (size_t v = (size_t)blockIdx.x * blockDim.x + threadIdx.x; v < n4;
         v += (size_t)gridDim.x * blockDim.x) {
        size_t e = v * 4;
        size_t t = e / K_DIM;
        size_t i = e % K_DIM;
        float4 f = reinterpret_cast<const float4*>(x)[v];
        __half h0 = __float2half_rn(f.x), h1 = __float2half_rn(f.y);
        __half h2 = __float2half_rn(f.z), h3 = __float2half_rn(f.w);
        __half l0 = __float2half_rn(f.x - __half2float(h0));
        __half l1 = __float2half_rn(f.y - __half2float(h1));
        __half l2 = __float2half_rn(f.z - __half2float(h2));
        __half l3 = __float2half_rn(f.w - __half2float(h3));
        __half2 hi0 = __halves2half2(h0, h1), hi1 = __halves2half2(h2, h3);
        __half2 lo0 = __halves2half2(l0, l1), lo1 = __halves2half2(l2, l3);
        uint2 uh, ul;
        uh.x = *reinterpret_cast<uint32_t*>(&hi0); uh.y = *reinterpret_cast<uint32_t*>(&hi1);
        ul.x = *reinterpret_cast<uint32_t*>(&lo0); ul.y = *reinterpret_cast<uint32_t*>(&lo1);
        reinterpret_cast<uint2*>(g_a + t * AK + i)[0] = uh;
        reinterpret_cast<uint2*>(g_a + t * AK + K_DIM + i)[0] = ul;
    }
}

__global__ void __launch_bounds__(256) wsplit_kernel(const float* __restrict__ w,
                                                     const float* __restrict__ s) {
    const size_t n4 = (size_t)O_DIM * K_DIM / 4;
    const int SCOLS = K_DIM / QB;  // 64
    for (size_t v = (size_t)blockIdx.x * blockDim.x + threadIdx.x; v < n4;
         v += (size_t)gridDim.x * blockDim.x) {
        size_t e = v * 4;
        size_t o = e / K_DIM;
        size_t i = e % K_DIM;
        float sc = s[(o >> 6) * SCOLS + (i >> 6)];
        float4 f = reinterpret_cast<const float4*>(w)[v];
        float d0 = f.x * sc, d1 = f.y * sc, d2 = f.z * sc, d3 = f.w * sc;
        __half h0 = __float2half_rn(d0), h1 = __float2half_rn(d1);
        __half h2 = __float2half_rn(d2), h3 = __float2half_rn(d3);
        __half l0 = __float2half_rn(d0 - __half2float(h0));
        __half l1 = __float2half_rn(d1 - __half2float(h1));
        __half l2 = __float2half_rn(d2 - __half2float(h2));
        __half l3 = __float2half_rn(d3 - __half2float(h3));
        __half2 hi0 = __halves2half2(h0, h1), hi1 = __halves2half2(h2, h3);
        __half2 lo0 = __halves2half2(l0, l1), lo1 = __halves2half2(l2, l3);
        uint2 uh, ul;
        uh.x = *reinterpret_cast<uint32_t*>(&hi0); uh.y = *reinterpret_cast<uint32_t*>(&hi1);
        ul.x = *reinterpret_cast<uint32_t*>(&lo0); ul.y = *reinterpret_cast<uint32_t*>(&lo1);
        reinterpret_cast<uint2*>(g_b + o * AK + i)[0] = uh;
        reinterpret_cast<uint2*>(g_b + o * AK + K_DIM + i)[0] = ul;
    }
}

// ---------------------------------------------------------------- tcgen05 helpers (feature-gated)
#if !defined(__CUDA_ARCH__) || defined(__CUDA_ARCH_FEAT_SM103_ALL)
__device__ __forceinline__ uint32_t elect_one() {
    uint32_t p;
    asm volatile("{\n\t.reg .pred p;\n\telect.sync _|p, 0xFFFFFFFF;\n\tselp.b32 %0, 1, 0, p;\n\t}" : "=r"(p));
    return p;
}
__device__ __forceinline__ void mbar_init(uint32_t mbar, uint32_t cnt) {
    asm volatile("mbarrier.init.shared.b64 [%0], %1;" :: "r"(mbar), "r"(cnt) : "memory");
}
__device__ __forceinline__ void mbar_inval(uint32_t mbar) {
    asm volatile("mbarrier.inval.shared.b64 [%0];" :: "r"(mbar) : "memory");
}
__device__ __forceinline__ void mbar_wait(uint32_t mbar, uint32_t parity) {
    asm volatile(
        "{\n\t.reg .pred P1;\n\t"
        "WL_%=:\n\t"
        "mbarrier.try_wait.parity.acquire.cta.shared::cta.b64 P1, [%0], %1, 0x989680;\n\t"
        "@P1 bra.uni WD_%=;\n\t"
        "bra.uni WL_%=;\n\t"
        "WD_%=:\n\t}"
        :: "r"(mbar), "r"(parity) : "memory");
}
__device__ __forceinline__ uint64_t make_desc(uint32_t addr) {
    constexpr uint64_t base =
        (uint64_t(2) << 61) | (uint64_t(1) << 46) | (uint64_t(64) << 32) | (uint64_t(1) << 16);
    return base | ((uint64_t)(addr >> 4) & 0x3FFF);
}
#if defined(__CUDA_ARCH_FEAT_SM103_ALL)
__device__ __forceinline__ void mma_f16_ss(uint32_t d, uint64_t a, uint64_t b,
                                           uint32_t idesc, uint32_t en) {
    asm volatile(
        "{\n\t.reg .pred p;\n\tsetp.ne.u32 p, %4, 0;\n\t"
        "tcgen05.mma.cta_group::1.kind::f16 [%0], %1, %2, %3, {%5, %5, %5, %5}, p;\n\t}"
        :: "r"(d), "l"(a), "l"(b), "r"(idesc), "r"(en), "r"(0u)
        : "memory");
}
__device__ __forceinline__ void tc_commit(uint32_t mbar) {
    asm volatile(
        "tcgen05.commit.cta_group::1.mbarrier::arrive::one.shared::cluster.b64 [%0];"
        :: "r"(mbar) : "memory");
}
#define TC_LD_X32(r, tmem_addr) \
    asm volatile( \
        "tcgen05.ld.sync.aligned.32x32b.x32.b32 " \
        "{%0, %1, %2, %3, %4, %5, %6, %7, " \
        " %8, %9, %10, %11, %12, %13, %14, %15, " \
        " %16, %17, %18, %19, %20, %21, %22, %23, " \
        " %24, %25, %26, %27, %28, %29, %30, %31}, [%32];" \
        : "=r"((r)[0]),  "=r"((r)[1]),  "=r"((r)[2]),  "=r"((r)[3]), \
          "=r"((r)[4]),  "=r"((r)[5]),  "=r"((r)[6]),  "=r"((r)[7]), \
          "=r"((r)[8]),  "=r"((r)[9]),  "=r"((r)[10]), "=r"((r)[11]), \
          "=r"((r)[12]), "=r"((r)[13]), "=r"((r)[14]), "=r"((r)[15]), \
          "=r"((r)[16]), "=r"((r)[17]), "=r"((r)[18]), "=r"((r)[19]), \
          "=r"((r)[20]), "=r"((r)[21]), "=r"((r)[22]), "=r"((r)[23]), \
          "=r"((r)[24]), "=r"((r)[25]), "=r"((r)[26]), "=r"((r)[27]), \
          "=r"((r)[28]), "=r"((r)[29]), "=r"((r)[30]), "=r"((r)[31]) \
        : "r"(tmem_addr))
#endif
#endif  // tcgen05 helpers

// ---------------------------------------------------------------- HMMA helpers (fallback)
#define LDSM_X4(r, addr) \
    asm volatile("ldmatrix.sync.aligned.m8n8.x4.shared.b16 {%0,%1,%2,%3}, [%4];" \
        : "=r"((r)[0]), "=r"((r)[1]), "=r"((r)[2]), "=r"((r)[3]) : "r"(addr))

#define MMA16816(c, a, b0, b1) \
    asm volatile("mma.sync.aligned.m16n8k16.row.col.f32.f16.f16.f32 " \
        "{%0,%1,%2,%3}, {%4,%5,%6,%7}, {%8,%9}, {%0,%1,%2,%3};" \
        : "+f"((c)[0]), "+f"((c)[1]), "+f"((c)[2]), "+f"((c)[3]) \
        : "r"((a)[0]), "r"((a)[1]), "r"((a)[2]), "r"((a)[3]), "r"(b0), "r"(b1))

// Per-stage K-block remap for the 3-product schedule:
//   kb in [0,64):    xh (A col kb)      * wh (B col kb)
//   kb in [64,128):  xh (A col kb-64)   * wl (B col kb)       [wl lives at +4096]
//   kb in [128,192): xl (A col kb-64)   * wh (B col kb-128)   [xl lives at +4096]
__device__ __forceinline__ int a_kblk(int kb) { return (kb < 128) ? (kb & 63) : (kb - 64); }
__device__ __forceinline__ int b_kblk(int kb) { return (kb < 128) ? kb : (kb - 128); }

// ---------------------------------------------------------------- GEMM
__global__ void __launch_bounds__(NTHREADS, 1) gemm_kernel(float* __restrict__ out) {
    extern __shared__ char smem[];
    const uint32_t sbase = smem_u32(smem);
    const int tid = threadIdx.x;
    const int wid = tid >> 5;
    const int lid = tid & 31;

    const int t0 = blockIdx.x * BM;   // m fastest-varying for B-tile L2 reuse
    const int o0 = blockIdx.y * BN;

#if defined(__CUDA_ARCH__) && !defined(__CUDA_ARCH_FEAT_SM103_ALL)
    // ================= HMMA fallback (compute_103 pass; never selected at runtime) =
    // Two sequential 128-row passes of the R3-proven 128x256 HMMA body.
    for (int half = 0; half < 2; half++) {
        const int t0h = t0 + half * 128;
        const __half* Ag = g_a + (size_t)t0h * AK;
        const __half* Bg = g_b + (size_t)o0 * AK;

        auto load_fb = [&](int st, int kb) {
            if (kb < KBLKS) {
                const uint32_t abase = sbase + st * FB_STAGE;
                const uint32_t bbase = abase + FB_A_BYTES;
                const int ak = a_kblk(kb) * BK;
                const int bk = b_kblk(kb) * BK;
                #pragma unroll
                for (int c = tid; c < (128 + 256) * 8; c += NTHREADS) {
                    int row = c >> 3, ch = c & 7;
                    if (row < 128)
                        cp_async16(abase + swz(row * 128 + ch * 16),
                                   Ag + (size_t)row * AK + ak + ch * 8);
                    else
                        cp_async16(bbase + swz((row - 128) * 128 + ch * 16),
                                   Bg + (size_t)(row - 128) * AK + bk + ch * 8);
                }
            }
            cp_commit();
        };

        const int warp_m = wid & 1;
        const int warp_n = wid >> 1;
        const int m_off = warp_m * 64;
        const int n_off = warp_n * 32;
        const int lrow = lid & 15;
        const int lc16 = lid >> 4;

        uint32_t preA[4], preB[2];
        #pragma unroll
        for (int mi = 0; mi < 4; mi++)
            preA[mi] = swz((uint32_t)((m_off + mi * 16 + lrow) * 128 + lc16 * 16));
        #pragma unroll
        for (int nj = 0; nj < 2; nj++)
            preB[nj] = swz((uint32_t)((n_off + nj * 16 + lrow) * 128 + lc16 * 16));

        float acc[4][4][4];
        #pragma unroll
        for (int mi = 0; mi < 4; mi++)
            #pragma unroll
            for (int ni = 0; ni < 4; ni++)
                #pragma unroll
                for (int q = 0; q < 4; q++) acc[mi][ni][q] = 0.f;

        load_fb(0, 0);
        load_fb(1, 1);

        for (int kb = 0; kb < KBLKS; kb++) {
            cp_wait<1>();
            __syncthreads();
            load_fb((kb + 2) % NSTAGE, kb + 2);

            const uint32_t sA = sbase + (kb % NSTAGE) * FB_STAGE;
            const uint32_t sB = sA + FB_A_BYTES;
            #pragma unroll
            for (int ks = 0; ks < 4; ks++) {
                const uint32_t xk = ks * 32;
                uint32_t a[4][4], b[2][4];
                #pragma unroll
                for (int mi = 0; mi < 4; mi++) LDSM_X4(a[mi], sA + (preA[mi] ^ xk));
                #pragma unroll
                for (int nj = 0; nj < 2; nj++) LDSM_X4(b[nj], sB + (preB[nj] ^ xk));
                #pragma unroll
                for (int mi = 0; mi < 4; mi++)
                    #pragma unroll
                    for (int ni = 0; ni < 4; ni++)
                        MMA16816(acc[mi][ni], a[mi], b[ni >> 1][ni & 1], b[ni >> 1][2 + (ni & 1)]);
            }
        }
        cp_wait<0>();
        __syncthreads();

        #pragma unroll
        for (int mi = 0; mi < 4; mi++) {
            const int r0 = t0h + m_off + mi * 16 + (lid >> 2);
            #pragma unroll
            for (int ni = 0; ni < 4; ni++) {
                const int c = o0 + n_off + ni * 8 + ((lid & 3) << 1);
                *reinterpret_cast<float2*>(out + (size_t)r0 * O_DIM + c) =
                    make_float2(acc[mi][ni][0], acc[mi][ni][1]);
                *reinterpret_cast<float2*>(out + (size_t)(r0 + 8) * O_DIM + c) =
                    make_float2(acc[mi][ni][2], acc[mi][ni][3]);
            }
        }
        __syncthreads();
    }
#else
#if defined(__CUDA_ARCH_FEAT_SM103_ALL)
    // ================= tcgen05 path (sm_103a cubin — the one that runs) ==========
    const __half* Ag = g_a + (size_t)t0 * AK;
    const __half* Bg = g_b + (size_t)o0 * AK;

    auto load_stage = [&](int st, int kb) {
        if (kb < KBLKS) {
            const uint32_t abase = sbase + st * STAGE_BYTES;
            const uint32_t bbase = abase + A_ST_BYTES;
            const int ak = a_kblk(kb) * BK;
            const int bk = b_kblk(kb) * BK;
            #pragma unroll
            for (int c = tid; c < (BM + BN) * 8; c += NTHREADS) {
                int row = c >> 3, ch = c & 7;
                if (row < BM)
                    cp_async16(abase + swz(row * 128 + ch * 16),
                               Ag + (size_t)row * AK + ak + ch * 8);
                else
                    cp_async16(bbase + swz((row - BM) * 128 + ch * 16),
                               Bg + (size_t)(row - BM) * AK + bk + ch * 8);
            }
        }
        cp_commit();
    };

    if (tid == 0) {
        #pragma unroll
        for (int st = 0; st < NSTAGE; st++) mbar_init(sbase + SMEM_BARS + st * 8, 1);
    }
    if (wid == 0) {
        asm volatile("tcgen05.alloc.cta_group::1.sync.aligned.shared::cta.b32 [%0], %1;"
                     :: "r"(sbase + SMEM_TMEMP), "r"(512u) : "memory");
        asm volatile("tcgen05.relinquish_alloc_permit.cta_group::1.sync.aligned;");
    }
    __syncthreads();
    uint32_t tmem;
    asm volatile("ld.shared.b32 %0, [%1];" : "=r"(tmem) : "r"(sbase + SMEM_TMEMP));

    for (int st = 0; st < NSTAGE; st++) load_stage(st, st);

    // idesc: dtype F32 (bit4), atype=btype=F16, N=128 -> 16<<17, M=128 -> 8<<24
    const uint32_t idesc = (1u << 4) | ((128u / 8) << 17) | ((128u / 16) << 24);
    int ph[NSTAGE] = {0, 0, 0};

    for (int kb = 0; kb < KBLKS; kb++) {
        const int st = kb % NSTAGE;
        cp_wait<NSTAGE - 1>();
        __syncthreads();

        if (wid == 0 && elect_one()) {
            asm volatile("fence.proxy.async.shared::cta;" ::: "memory");
            const uint32_t stb = sbase + st * STAGE_BYTES;
            const uint64_t ad0 = make_desc(stb);
            const uint64_t ad1 = make_desc(stb + A_ST_BYTES / 2);          // A rows 128-255
            const uint64_t bd0 = make_desc(stb + A_ST_BYTES);
            const uint64_t bd1 = make_desc(stb + A_ST_BYTES + B_ST_BYTES / 2);  // B rows 128-255
            #pragma unroll
            for (int k = 0; k < 4; k++) {  // 4 x K16 steps per K64 stage
                const uint32_t acc = (kb > 0 || k > 0) ? 1u : 0u;
                mma_f16_ss(tmem,       ad0 + k * 2, bd0 + k * 2, idesc, acc);  // (m0,n0)
                mma_f16_ss(tmem + 128, ad0 + k * 2, bd1 + k * 2, idesc, acc);  // (m0,n1)
                mma_f16_ss(tmem + 256, ad1 + k * 2, bd0 + k * 2, idesc, acc);  // (m1,n0)
                mma_f16_ss(tmem + 384, ad1 + k * 2, bd1 + k * 2, idesc, acc);  // (m1,n1)
            }
            tc_commit(sbase + SMEM_BARS + st * 8);
        }

        const int nkb = kb + NSTAGE;
        if (nkb < KBLKS) {
            mbar_wait(sbase + SMEM_BARS + st * 8, (uint32_t)ph[st]);
            ph[st] ^= 1;
            load_stage(st, nkb);
        }
    }

    const int lst = (KBLKS - 1) % NSTAGE;
    mbar_wait(sbase + SMEM_BARS + lst * 8, (uint32_t)ph[lst]);
    asm volatile("tcgen05.fence::after_thread_sync;" ::: "memory");

    // Epilogue: 16 warps; warp -> (row subpartition, D tile).
    // D tiles: col 0:(m0,n0), 128:(m0,n1), 256:(m1,n0), 384:(m1,n1)
    {
        const int sub = wid & 3;          // 32-row subpartition
        const int dt = wid >> 2;          // 0..3 D tile
        const int mi = dt >> 1;
        const int ni = dt & 1;
        float* orow = out + (size_t)(t0 + mi * 128 + sub * 32 + lid) * O_DIM
                      + o0 + ni * 128;
        #pragma unroll
        for (int cb = 0; cb < 4; cb++) {
            uint32_t r[32];
            TC_LD_X32(r, tmem + dt * 128 + cb * 32);
            asm volatile("tcgen05.wait::ld.sync.aligned;" ::: "memory");
            float4* dst = reinterpret_cast<float4*>(orow + cb * 32);
            #pragma unroll
            for (int q = 0; q < 8; q++)
                dst[q] = make_float4(__uint_as_float(r[4 * q + 0]),
                                     __uint_as_float(r[4 * q + 1]),
                                     __uint_as_float(r[4 * q + 2]),
                                     __uint_as_float(r[4 * q + 3]));
        }
    }

    __syncthreads();
    if (tid == 0) {
        #pragma unroll
        for (int st = 0; st < NSTAGE; st++) mbar_inval(sbase + SMEM_BARS + st * 8);
    }
    __syncthreads();
    if (wid == 0) {
        asm volatile("tcgen05.dealloc.cta_group::1.sync.aligned.b32 %0, %1;"
                     :: "r"(tmem), "r"(512u));
    }
#endif
#endif
}

// ---------------------------------------------------------------- launch
extern "C" void kernel_launch(void* const* d_in, const int* in_sizes, int n_in,
                              void* d_out, int out_size) {
    (void)in_sizes; (void)n_in; (void)out_size;
    const float* x = (const float*)d_in[0];
    const float* w = (const float*)d_in[1];
    const float* s = (const float*)d_in[2];
    float* out = (float*)d_out;

    xsplit_kernel<<<2048, 256>>>(x);
    wsplit_kernel<<<2048, 256>>>(w, s);

    cudaFuncSetAttribute(gemm_kernel, cudaFuncAttributeMaxDynamicSharedMemorySize, SMEM_TOTAL);
    dim3 grid(T_DIM / BM, O_DIM / BN);  // (32, 43), m fastest
    gemm_kernel<<<grid, NTHREADS, SMEM_TOTAL>>>(out);
}

// round 15
// speedup vs baseline: 1.5772x; 1.5772x over previous
#include <cuda_runtime.h>
#include <cuda_fp16.h>
#include <cstdint>

// Problem dims
#define T_DIM 8192
#define K_DIM 4096
#define O_DIM 11008
#define QB    64

// Two-term split: A row = [xh(4096) | xl(4096)], B row = [wh(4096) | wl(4096)]
#define AK 8192

// GEMM tiling (R13 constants; HMMA path untouched)
#define BM 128
#define BN 256
#define BK 64                       // 64 fp16 = 128 B per row = one SW128 atom row
#define NSTAGE 3                    // HMMA fallback stage count (unchanged)
#define TC_NSTAGE 4                 // tcgen05 path: 4 stages for load/MMA overlap
#define KBLKS 192                   // 64 (xh*wh) + 64 (xh*wl) + 64 (xl*wh)
#define NTHREADS 512

#define A_ST_BYTES (BM * 128)       // 16384
#define B_ST_BYTES (BN * 128)       // 32768
#define STAGE_BYTES (A_ST_BYTES + B_ST_BYTES)  // 49152
#define SMEM_BARS  (TC_NSTAGE * STAGE_BYTES)   // 196608
#define SMEM_TMEMP (SMEM_BARS + TC_NSTAGE * 8)
#define SMEM_TOTAL (SMEM_TMEMP + 8)            // 196648

// fp16 scratch (static device arrays: allocation-free contract)
__device__ __align__(16) __half g_a[(size_t)T_DIM * AK];   // [xh | xl]
__device__ __align__(16) __half g_b[(size_t)O_DIM * AK];   // [wh | wl]

// ---------------------------------------------------------------- helpers
__device__ __forceinline__ uint32_t smem_u32(const void* p) {
    uint32_t a;
    asm("{ .reg .u64 t; cvta.to.shared.u64 t, %1; cvt.u32.u64 %0, t; }" : "=r"(a) : "l"(p));
    return a;
}
__device__ __forceinline__ uint32_t swz(uint32_t off) { return off ^ ((off >> 3) & 0x70); }

__device__ __forceinline__ void cp_async16(uint32_t dst, const void* src) {
    asm volatile("cp.async.cg.shared.global [%0], [%1], 16;\n" :: "r"(dst), "l"(src));
}
__device__ __forceinline__ void cp_commit() { asm volatile("cp.async.commit_group;\n" ::: "memory"); }
template <int N>
__device__ __forceinline__ void cp_wait() { asm volatile("cp.async.wait_group %0;\n" :: "n"(N) : "memory"); }

// ---------------------------------------------------------------- prep kernels
__global__ void __launch_bounds__(256) xsplit_kernel(const float* __restrict__ x) {
    const size_t n4 = (size_t)T_DIM * K_DIM / 4;
    for (size_t v = (size_t)blockIdx.x * blockDim.x + threadIdx.x; v < n4;
         v += (size_t)gridDim.x * blockDim.x) {
        size_t e = v * 4;
        size_t t = e / K_DIM;
        size_t i = e % K_DIM;
        float4 f = reinterpret_cast<const float4*>(x)[v];
        __half h0 = __float2half_rn(f.x), h1 = __float2half_rn(f.y);
        __half h2 = __float2half_rn(f.z), h3 = __float2half_rn(f.w);
        __half l0 = __float2half_rn(f.x - __half2float(h0));
        __half l1 = __float2half_rn(f.y - __half2float(h1));
        __half l2 = __float2half_rn(f.z - __half2float(h2));
        __half l3 = __float2half_rn(f.w - __half2float(h3));
        __half2 hi0 = __halves2half2(h0, h1), hi1 = __halves2half2(h2, h3);
        __half2 lo0 = __halves2half2(l0, l1), lo1 = __halves2half2(l2, l3);
        uint2 uh, ul;
        uh.x = *reinterpret_cast<uint32_t*>(&hi0); uh.y = *reinterpret_cast<uint32_t*>(&hi1);
        ul.x = *reinterpret_cast<uint32_t*>(&lo0); ul.y = *reinterpret_cast<uint32_t*>(&lo1);
        reinterpret_cast<uint2*>(g_a + t * AK + i)[0] = uh;
        reinterpret_cast<uint2*>(g_a + t * AK + K_DIM + i)[0] = ul;
    }
}

__global__ void __launch_bounds__(256) wsplit_kernel(const float* __restrict__ w,
                                                     const float* __restrict__ s) {
    const size_t n4 = (size_t)O_DIM * K_DIM / 4;
    const int SCOLS = K_DIM / QB;  // 64
    for (size_t v = (size_t)blockIdx.x * blockDim.x + threadIdx.x; v < n4;
         v += (size_t)gridDim.x * blockDim.x) {
        size_t e = v * 4;
        size_t o = e / K_DIM;
        size_t i = e % K_DIM;
        float sc = s[(o >> 6) * SCOLS + (i >> 6)];
        float4 f = reinterpret_cast<const float4*>(w)[v];
        float d0 = f.x * sc, d1 = f.y * sc, d2 = f.z * sc, d3 = f.w * sc;
        __half h0 = __float2half_rn(d0), h1 = __float2half_rn(d1);
        __half h2 = __float2half_rn(d2), h3 = __float2half_rn(d3);
        __half l0 = __float2half_rn(d0 - __half2float(h0));
        __half l1 = __float2half_rn(d1 - __half2float(h1));
        __half l2 = __float2half_rn(d2 - __half2float(h2));
        __half l3 = __float2half_rn(d3 - __half2float(h3));
        __half2 hi0 = __halves2half2(h0, h1), hi1 = __halves2half2(h2, h3);
        __half2 lo0 = __halves2half2(l0, l1), lo1 = __halves2half2(l2, l3);
        uint2 uh, ul;
        uh.x = *reinterpret_cast<uint32_t*>(&hi0); uh.y = *reinterpret_cast<uint32_t*>(&hi1);
        ul.x = *reinterpret_cast<uint32_t*>(&lo0); ul.y = *reinterpret_cast<uint32_t*>(&lo1);
        reinterpret_cast<uint2*>(g_b + o * AK + i)[0] = uh;
        reinterpret_cast<uint2*>(g_b + o * AK + K_DIM + i)[0] = ul;
    }
}

// ---------------------------------------------------------------- tcgen05 helpers (feature-gated)
#if !defined(__CUDA_ARCH__) || defined(__CUDA_ARCH_FEAT_SM103_ALL)
__device__ __forceinline__ uint32_t elect_one() {
    uint32_t p;
    asm volatile("{\n\t.reg .pred p;\n\telect.sync _|p, 0xFFFFFFFF;\n\tselp.b32 %0, 1, 0, p;\n\t}" : "=r"(p));
    return p;
}
__device__ __forceinline__ void mbar_init(uint32_t mbar, uint32_t cnt) {
    asm volatile("mbarrier.init.shared.b64 [%0], %1;" :: "r"(mbar), "r"(cnt) : "memory");
}
__device__ __forceinline__ void mbar_inval(uint32_t mbar) {
    asm volatile("mbarrier.inval.shared.b64 [%0];" :: "r"(mbar) : "memory");
}
__device__ __forceinline__ void mbar_wait(uint32_t mbar, uint32_t parity) {
    asm volatile(
        "{\n\t.reg .pred P1;\n\t"
        "WL_%=:\n\t"
        "mbarrier.try_wait.parity.acquire.cta.shared::cta.b64 P1, [%0], %1, 0x989680;\n\t"
        "@P1 bra.uni WD_%=;\n\t"
        "bra.uni WL_%=;\n\t"
        "WD_%=:\n\t}"
        :: "r"(mbar), "r"(parity) : "memory");
}
__device__ __forceinline__ uint64_t make_desc(uint32_t addr) {
    constexpr uint64_t base =
        (uint64_t(2) << 61) | (uint64_t(1) << 46) | (uint64_t(64) << 32) | (uint64_t(1) << 16);
    return base | ((uint64_t)(addr >> 4) & 0x3FFF);
}
#if defined(__CUDA_ARCH_FEAT_SM103_ALL)
__device__ __forceinline__ void mma_f16_ss(uint32_t d, uint64_t a, uint64_t b,
                                           uint32_t idesc, uint32_t en) {
    asm volatile(
        "{\n\t.reg .pred p;\n\tsetp.ne.u32 p, %4, 0;\n\t"
        "tcgen05.mma.cta_group::1.kind::f16 [%0], %1, %2, %3, {%5, %5, %5, %5}, p;\n\t}"
        :: "r"(d), "l"(a), "l"(b), "r"(idesc), "r"(en), "r"(0u)
        : "memory");
}
__device__ __forceinline__ void tc_commit(uint32_t mbar) {
    asm volatile(
        "tcgen05.commit.cta_group::1.mbarrier::arrive::one.shared::cluster.b64 [%0];"
        :: "r"(mbar) : "memory");
}
#define TC_LD_X32(r, tmem_addr) \
    asm volatile( \
        "tcgen05.ld.sync.aligned.32x32b.x32.b32 " \
        "{%0, %1, %2, %3, %4, %5, %6, %7, " \
        " %8, %9, %10, %11, %12, %13, %14, %15, " \
        " %16, %17, %18, %19, %20, %21, %22, %23, " \
        " %24, %25, %26, %27, %28, %29, %30, %31}, [%32];" \
        : "=r"((r)[0]),  "=r"((r)[1]),  "=r"((r)[2]),  "=r"((r)[3]), \
          "=r"((r)[4]),  "=r"((r)[5]),  "=r"((r)[6]),  "=r"((r)[7]), \
          "=r"((r)[8]),  "=r"((r)[9]),  "=r"((r)[10]), "=r"((r)[11]), \
          "=r"((r)[12]), "=r"((r)[13]), "=r"((r)[14]), "=r"((r)[15]), \
          "=r"((r)[16]), "=r"((r)[17]), "=r"((r)[18]), "=r"((r)[19]), \
          "=r"((r)[20]), "=r"((r)[21]), "=r"((r)[22]), "=r"((r)[23]), \
          "=r"((r)[24]), "=r"((r)[25]), "=r"((r)[26]), "=r"((r)[27]), \
          "=r"((r)[28]), "=r"((r)[29]), "=r"((r)[30]), "=r"((r)[31]) \
        : "r"(tmem_addr))
#endif
#endif  // tcgen05 helpers

// ---------------------------------------------------------------- HMMA helpers (baseline PTX)
#define LDSM_X4(r, addr) \
    asm volatile("ldmatrix.sync.aligned.m8n8.x4.shared.b16 {%0,%1,%2,%3}, [%4];" \
        : "=r"((r)[0]), "=r"((r)[1]), "=r"((r)[2]), "=r"((r)[3]) : "r"(addr))

#define MMA16816(c, a, b0, b1) \
    asm volatile("mma.sync.aligned.m16n8k16.row.col.f32.f16.f16.f32 " \
        "{%0,%1,%2,%3}, {%4,%5,%6,%7}, {%8,%9}, {%0,%1,%2,%3};" \
        : "+f"((c)[0]), "+f"((c)[1]), "+f"((c)[2]), "+f"((c)[3]) \
        : "r"((a)[0]), "r"((a)[1]), "r"((a)[2]), "r"((a)[3]), "r"(b0), "r"(b1))

// Per-stage K-block remap for the 3-product schedule:
//   kb in [0,64):    xh (A col kb)      * wh (B col kb)
//   kb in [64,128):  xh (A col kb-64)   * wl (B col kb)       [wl lives at +4096]
//   kb in [128,192): xl (A col kb-64)   * wh (B col kb-128)   [xl lives at +4096]
__device__ __forceinline__ int a_kblk(int kb) { return (kb < 128) ? (kb & 63) : (kb - 64); }
__device__ __forceinline__ int b_kblk(int kb) { return (kb < 128) ? kb : (kb - 128); }

// ---------------------------------------------------------------- GEMM
__global__ void __launch_bounds__(NTHREADS, 1) gemm_kernel(float* __restrict__ out) {
    extern __shared__ char smem[];
    const uint32_t sbase = smem_u32(smem);
    const int tid = threadIdx.x;
    const int wid = tid >> 5;
    const int lid = tid & 31;

    const int t0 = blockIdx.x * BM;   // m fastest-varying for B-tile L2 reuse
    const int o0 = blockIdx.y * BN;

    const __half* Ag = g_a + (size_t)t0 * AK;
    const __half* Bg = g_b + (size_t)o0 * AK;

    auto load_stage = [&](int st, int kb) {
        if (kb < KBLKS) {
            const uint32_t abase = sbase + st * STAGE_BYTES;
            const uint32_t bbase = abase + A_ST_BYTES;
            const int ak = a_kblk(kb) * BK;
            const int bk = b_kblk(kb) * BK;
            #pragma unroll
            for (int c = tid; c < (BM + BN) * 8; c += NTHREADS) {
                int row = c >> 3, ch = c & 7;
                if (row < BM)
                    cp_async16(abase + swz(row * 128 + ch * 16),
                               Ag + (size_t)row * AK + ak + ch * 8);
                else
                    cp_async16(bbase + swz((row - BM) * 128 + ch * 16),
                               Bg + (size_t)(row - BM) * AK + bk + ch * 8);
            }
        }
        cp_commit();
    };

#if defined(__CUDA_ARCH__) && !defined(__CUDA_ARCH_FEAT_SM103_ALL)
    // ================= HMMA fallback path (sm_103 baseline PTX) — R13-identical ====
    const int warp_m = wid & 1;
    const int warp_n = wid >> 1;
    const int m_off = warp_m * 64;
    const int n_off = warp_n * 32;
    const int lrow = lid & 15;
    const int lc16 = lid >> 4;

    uint32_t preA[4], preB[2];
    #pragma unroll
    for (int mi = 0; mi < 4; mi++)
        preA[mi] = swz((uint32_t)((m_off + mi * 16 + lrow) * 128 + lc16 * 16));
    #pragma unroll
    for (int nj = 0; nj < 2; nj++)
        preB[nj] = swz((uint32_t)((n_off + nj * 16 + lrow) * 128 + lc16 * 16));

    float acc[4][4][4];
    #pragma unroll
    for (int mi = 0; mi < 4; mi++)
        #pragma unroll
        for (int ni = 0; ni < 4; ni++)
            #pragma unroll
            for (int q = 0; q < 4; q++) acc[mi][ni][q] = 0.f;

    load_stage(0, 0);
    load_stage(1, 1);

    for (int kb = 0; kb < KBLKS; kb++) {
        cp_wait<1>();
        __syncthreads();
        load_stage((kb + 2) % NSTAGE, kb + 2);

        const uint32_t sA = sbase + (kb % NSTAGE) * STAGE_BYTES;
        const uint32_t sB = sA + A_ST_BYTES;
        #pragma unroll
        for (int ks = 0; ks < 4; ks++) {
            const uint32_t xk = ks * 32;
            uint32_t a[4][4], b[2][4];
            #pragma unroll
            for (int mi = 0; mi < 4; mi++) LDSM_X4(a[mi], sA + (preA[mi] ^ xk));
            #pragma unroll
            for (int nj = 0; nj < 2; nj++) LDSM_X4(b[nj], sB + (preB[nj] ^ xk));
            #pragma unroll
            for (int mi = 0; mi < 4; mi++)
                #pragma unroll
                for (int ni = 0; ni < 4; ni++)
                    MMA16816(acc[mi][ni], a[mi], b[ni >> 1][ni & 1], b[ni >> 1][2 + (ni & 1)]);
        }
    }

    #pragma unroll
    for (int mi = 0; mi < 4; mi++) {
        const int r0 = t0 + m_off + mi * 16 + (lid >> 2);
        #pragma unroll
        for (int ni = 0; ni < 4; ni++) {
            const int c = o0 + n_off + ni * 8 + ((lid & 3) << 1);
            *reinterpret_cast<float2*>(out + (size_t)r0 * O_DIM + c) =
                make_float2(acc[mi][ni][0], acc[mi][ni][1]);
            *reinterpret_cast<float2*>(out + (size_t)(r0 + 8) * O_DIM + c) =
                make_float2(acc[mi][ni][2], acc[mi][ni][3]);
        }
    }
#else
#if defined(__CUDA_ARCH_FEAT_SM103_ALL)
    // ================= tcgen05 path: 4-stage overlapped pipeline =================
    if (tid == 0) {
        #pragma unroll
        for (int st = 0; st < TC_NSTAGE; st++) mbar_init(sbase + SMEM_BARS + st * 8, 1);
    }
    if (wid == 0) {
        asm volatile("tcgen05.alloc.cta_group::1.sync.aligned.shared::cta.b32 [%0], %1;"
                     :: "r"(sbase + SMEM_TMEMP), "r"(256u) : "memory");
        asm volatile("tcgen05.relinquish_alloc_permit.cta_group::1.sync.aligned;");
    }
    __syncthreads();
    uint32_t tmem;
    asm volatile("ld.shared.b32 %0, [%1];" : "=r"(tmem) : "r"(sbase + SMEM_TMEMP));

    // prologue: 3 of 4 stages in flight
    load_stage(0, 0);
    load_stage(1, 1);
    load_stage(2, 2);

    const uint32_t idesc = (1u << 4) | ((128u / 8) << 17) | ((128u / 16) << 24);
    int ph[TC_NSTAGE] = {0, 0, 0, 0};

    for (int kb = 0; kb < KBLKS; kb++) {
        const int st = kb & (TC_NSTAGE - 1);
        cp_wait<2>();           // data kb resident (uniform 1 commit/iter below)
        __syncthreads();

        if (wid == 0 && elect_one()) {
            asm volatile("fence.proxy.async.shared::cta;" ::: "memory");
            const uint64_t ad = make_desc(sbase + st * STAGE_BYTES);
            const uint64_t bd = make_desc(sbase + st * STAGE_BYTES + A_ST_BYTES);
            #pragma unroll
            for (int k = 0; k < 4; k++) {
                const uint32_t acc = (kb > 0 || k > 0) ? 1u : 0u;
                mma_f16_ss(tmem,       ad + k * 2, bd + k * 2,        idesc, acc);
                mma_f16_ss(tmem + 128, ad + k * 2, bd + 1024 + k * 2, idesc, acc);
            }
            tc_commit(sbase + SMEM_BARS + st * 8);
        }

        // Refill the stage MMA(kb-1) used — already complete (fast TRYWAIT) —
        // so loads overlap with MMA(kb). Uniform commit keeps cp_wait<2> exact.
        {
            const int nkb = kb + 3;
            const int pst = nkb & (TC_NSTAGE - 1);   // == (kb-1) & 3
            if (nkb < KBLKS && kb >= 1) {
                mbar_wait(sbase + SMEM_BARS + pst * 8, (uint32_t)ph[pst]);
                ph[pst] ^= 1;
            }
            load_stage(pst, nkb);   // loads iff nkb<KBLKS; ALWAYS commits
        }
    }

    // Final MMA group: last commit covers all prior MMAs.
    {
        const int lst = (KBLKS - 1) & (TC_NSTAGE - 1);
        mbar_wait(sbase + SMEM_BARS + lst * 8, (uint32_t)ph[lst]);
        ph[lst] ^= 1;
    }
    asm volatile("tcgen05.fence::after_thread_sync;" ::: "memory");

    // Epilogue (R13-identical)
    {
        const int rowsub = (wid & 3) * 32;
        const int cbase0 = (wid >> 2) * 64;
        float* orow = out + (size_t)(t0 + rowsub + lid) * O_DIM + o0 + cbase0;
        #pragma unroll
        for (int cb = 0; cb < 2; cb++) {
            uint32_t r[32];
            TC_LD_X32(r, tmem + cbase0 + cb * 32);
            asm volatile("tcgen05.wait::ld.sync.aligned;" ::: "memory");
            float4* dst = reinterpret_cast<float4*>(orow + cb * 32);
            #pragma unroll
            for (int q = 0; q < 8; q++)
                dst[q] = make_float4(__uint_as_float(r[4 * q + 0]),
                                     __uint_as_float(r[4 * q + 1]),
                                     __uint_as_float(r[4 * q + 2]),
                                     __uint_as_float(r[4 * q + 3]));
        }
    }

    __syncthreads();
    if (tid == 0) {
        #pragma unroll
        for (int st = 0; st < TC_NSTAGE; st++) mbar_inval(sbase + SMEM_BARS + st * 8);
    }
    __syncthreads();
    if (wid == 0) {
        asm volatile("tcgen05.dealloc.cta_group::1.sync.aligned.b32 %0, %1;"
                     :: "r"(tmem), "r"(256u));
    }
#endif
#endif
}

// ---------------------------------------------------------------- launch
extern "C" void kernel_launch(void* const* d_in, const int* in_sizes, int n_in,
                              void* d_out, int out_size) {
    (void)in_sizes; (void)n_in; (void)out_size;
    const float* x = (const float*)d_in[0];
    const float* w = (const float*)d_in[1];
    const float* s = (const float*)d_in[2];
    float* out = (float*)d_out;

    xsplit_kernel<<<2048, 256>>>(x);
    wsplit_kernel<<<2048, 256>>>(w, s);

    cudaFuncSetAttribute(gemm_kernel, cudaFuncAttributeMaxDynamicSharedMemorySize, SMEM_TOTAL);
    dim3 grid(T_DIM / BM, O_DIM / BN);  // (64, 43), m fastest
    gemm_kernel<<<grid, NTHREADS, SMEM_TOTAL>>>(out);
}

// round 16
// speedup vs baseline: 1.6951x; 1.0747x over previous
#include <cuda_runtime.h>
#include <cuda_fp16.h>
#include <cstdint>

// Problem dims
#define T_DIM 8192
#define K_DIM 4096
#define O_DIM 11008
#define QB    64

// Two-term split: A row = [xh(4096) | xl(4096)], B row = [wh(4096) | wl(4096)]
#define AK 8192

// GEMM tiling
#define BM 128
#define BN 256
#define BK 64                       // 64 fp16 = 128 B per row
#define NSTAGE 3                    // HMMA fallback ring (unchanged, never runs)
#define KBLKS 192                   // fallback 3-product schedule
#define NTHREADS 512

#define A_ST_BYTES (BM * 128)       // 16384 (fallback)
#define B_ST_BYTES (BN * 128)       // 32768 (fallback)
#define STAGE_BYTES (A_ST_BYTES + B_ST_BYTES)  // 49152 (fallback)

// tcgen05 fused-K stage: [xh 16K | xl 16K | wh 32K | wl 32K] = 96 KB, 2-stage ring
#define TC_STAGE 98304
#define TC_KBLKS 64
#define SMEM_BARS  (2 * TC_STAGE)              // 196608
#define SMEM_TMEMP (SMEM_BARS + 2 * 8)
#define SMEM_TOTAL (SMEM_TMEMP + 8)            // 196632

// fp16 scratch (static device arrays: allocation-free contract)
__device__ __align__(16) __half g_a[(size_t)T_DIM * AK];   // [xh | xl]
__device__ __align__(16) __half g_b[(size_t)O_DIM * AK];   // [wh | wl]

// ---------------------------------------------------------------- helpers
__device__ __forceinline__ uint32_t smem_u32(const void* p) {
    uint32_t a;
    asm("{ .reg .u64 t; cvta.to.shared.u64 t, %1; cvt.u32.u64 %0, t; }" : "=r"(a) : "l"(p));
    return a;
}
__device__ __forceinline__ uint32_t swz(uint32_t off) { return off ^ ((off >> 3) & 0x70); }

__device__ __forceinline__ void cp_async16(uint32_t dst, const void* src) {
    asm volatile("cp.async.cg.shared.global [%0], [%1], 16;\n" :: "r"(dst), "l"(src));
}
__device__ __forceinline__ void cp_commit() { asm volatile("cp.async.commit_group;\n" ::: "memory"); }
template <int N>
__device__ __forceinline__ void cp_wait() { asm volatile("cp.async.wait_group %0;\n" :: "n"(N) : "memory"); }

// ---------------------------------------------------------------- prep kernels
__global__ void __launch_bounds__(256) xsplit_kernel(const float* __restrict__ x) {
    const size_t n4 = (size_t)T_DIM * K_DIM / 4;
    for (size_t v = (size_t)blockIdx.x * blockDim.x + threadIdx.x; v < n4;
         v += (size_t)gridDim.x * blockDim.x) {
        size_t e = v * 4;
        size_t t = e / K_DIM;
        size_t i = e % K_DIM;
        float4 f = reinterpret_cast<const float4*>(x)[v];
        __half h0 = __float2half_rn(f.x), h1 = __float2half_rn(f.y);
        __half h2 = __float2half_rn(f.z), h3 = __float2half_rn(f.w);
        __half l0 = __float2half_rn(f.x - __half2float(h0));
        __half l1 = __float2half_rn(f.y - __half2float(h1));
        __half l2 = __float2half_rn(f.z - __half2float(h2));
        __half l3 = __float2half_rn(f.w - __half2float(h3));
        __half2 hi0 = __halves2half2(h0, h1), hi1 = __halves2half2(h2, h3);
        __half2 lo0 = __halves2half2(l0, l1), lo1 = __halves2half2(l2, l3);
        uint2 uh, ul;
        uh.x = *reinterpret_cast<uint32_t*>(&hi0); uh.y = *reinterpret_cast<uint32_t*>(&hi1);
        ul.x = *reinterpret_cast<uint32_t*>(&lo0); ul.y = *reinterpret_cast<uint32_t*>(&lo1);
        reinterpret_cast<uint2*>(g_a + t * AK + i)[0] = uh;
        reinterpret_cast<uint2*>(g_a + t * AK + K_DIM + i)[0] = ul;
    }
}

__global__ void __launch_bounds__(256) wsplit_kernel(const float* __restrict__ w,
                                                     const float* __restrict__ s) {
    const size_t n4 = (size_t)O_DIM * K_DIM / 4;
    const int SCOLS = K_DIM / QB;  // 64
    for (size_t v = (size_t)blockIdx.x * blockDim.x + threadIdx.x; v < n4;
         v += (size_t)gridDim.x * blockDim.x) {
        size_t e = v * 4;
        size_t o = e / K_DIM;
        size_t i = e % K_DIM;
        float sc = s[(o >> 6) * SCOLS + (i >> 6)];
        float4 f = reinterpret_cast<const float4*>(w)[v];
        float d0 = f.x * sc, d1 = f.y * sc, d2 = f.z * sc, d3 = f.w * sc;
        __half h0 = __float2half_rn(d0), h1 = __float2half_rn(d1);
        __half h2 = __float2half_rn(d2), h3 = __float2half_rn(d3);
        __half l0 = __float2half_rn(d0 - __half2float(h0));
        __half l1 = __float2half_rn(d1 - __half2float(h1));
        __half l2 = __float2half_rn(d2 - __half2float(h2));
        __half l3 = __float2half_rn(d3 - __half2float(h3));
        __half2 hi0 = __halves2half2(h0, h1), hi1 = __halves2half2(h2, h3);
        __half2 lo0 = __halves2half2(l0, l1), lo1 = __halves2half2(l2, l3);
        uint2 uh, ul;
        uh.x = *reinterpret_cast<uint32_t*>(&hi0); uh.y = *reinterpret_cast<uint32_t*>(&hi1);
        ul.x = *reinterpret_cast<uint32_t*>(&lo0); ul.y = *reinterpret_cast<uint32_t*>(&lo1);
        reinterpret_cast<uint2*>(g_b + o * AK + i)[0] = uh;
        reinterpret_cast<uint2*>(g_b + o * AK + K_DIM + i)[0] = ul;
    }
}

// ---------------------------------------------------------------- tcgen05 helpers (feature-gated)
#if !defined(__CUDA_ARCH__) || defined(__CUDA_ARCH_FEAT_SM103_ALL)
__device__ __forceinline__ uint32_t elect_one() {
    uint32_t p;
    asm volatile("{\n\t.reg .pred p;\n\telect.sync _|p, 0xFFFFFFFF;\n\tselp.b32 %0, 1, 0, p;\n\t}" : "=r"(p));
    return p;
}
__device__ __forceinline__ void mbar_init(uint32_t mbar, uint32_t cnt) {
    asm volatile("mbarrier.init.shared.b64 [%0], %1;" :: "r"(mbar), "r"(cnt) : "memory");
}
__device__ __forceinline__ void mbar_inval(uint32_t mbar) {
    asm volatile("mbarrier.inval.shared.b64 [%0];" :: "r"(mbar) : "memory");
}
__device__ __forceinline__ void mbar_wait(uint32_t mbar, uint32_t parity) {
    asm volatile(
        "{\n\t.reg .pred P1;\n\t"
        "WL_%=:\n\t"
        "mbarrier.try_wait.parity.acquire.cta.shared::cta.b64 P1, [%0], %1, 0x989680;\n\t"
        "@P1 bra.uni WD_%=;\n\t"
        "bra.uni WL_%=;\n\t"
        "WD_%=:\n\t}"
        :: "r"(mbar), "r"(parity) : "memory");
}
__device__ __forceinline__ uint64_t make_desc(uint32_t addr) {
    constexpr uint64_t base =
        (uint64_t(2) << 61) | (uint64_t(1) << 46) | (uint64_t(64) << 32) | (uint64_t(1) << 16);
    return base | ((uint64_t)(addr >> 4) & 0x3FFF);
}
#if defined(__CUDA_ARCH_FEAT_SM103_ALL)
__device__ __forceinline__ void mma_f16_ss(uint32_t d, uint64_t a, uint64_t b,
                                           uint32_t idesc, uint32_t en) {
    asm volatile(
        "{\n\t.reg .pred p;\n\tsetp.ne.u32 p, %4, 0;\n\t"
        "tcgen05.mma.cta_group::1.kind::f16 [%0], %1, %2, %3, {%5, %5, %5, %5}, p;\n\t}"
        :: "r"(d), "l"(a), "l"(b), "r"(idesc), "r"(en), "r"(0u)
        : "memory");
}
__device__ __forceinline__ void tc_commit(uint32_t mbar) {
    asm volatile(
        "tcgen05.commit.cta_group::1.mbarrier::arrive::one.shared::cluster.b64 [%0];"
        :: "r"(mbar) : "memory");
}
#define TC_LD_X32(r, tmem_addr) \
    asm volatile( \
        "tcgen05.ld.sync.aligned.32x32b.x32.b32 " \
        "{%0, %1, %2, %3, %4, %5, %6, %7, " \
        " %8, %9, %10, %11, %12, %13, %14, %15, " \
        " %16, %17, %18, %19, %20, %21, %22, %23, " \
        " %24, %25, %26, %27, %28, %29, %30, %31}, [%32];" \
        : "=r"((r)[0]),  "=r"((r)[1]),  "=r"((r)[2]),  "=r"((r)[3]), \
          "=r"((r)[4]),  "=r"((r)[5]),  "=r"((r)[6]),  "=r"((r)[7]), \
          "=r"((r)[8]),  "=r"((r)[9]),  "=r"((r)[10]), "=r"((r)[11]), \
          "=r"((r)[12]), "=r"((r)[13]), "=r"((r)[14]), "=r"((r)[15]), \
          "=r"((r)[16]), "=r"((r)[17]), "=r"((r)[18]), "=r"((r)[19]), \
          "=r"((r)[20]), "=r"((r)[21]), "=r"((r)[22]), "=r"((r)[23]), \
          "=r"((r)[24]), "=r"((r)[25]), "=r"((r)[26]), "=r"((r)[27]), \
          "=r"((r)[28]), "=r"((r)[29]), "=r"((r)[30]), "=r"((r)[31]) \
        : "r"(tmem_addr))
#endif
#endif  // tcgen05 helpers

// ---------------------------------------------------------------- HMMA helpers (baseline PTX)
#define LDSM_X4(r, addr) \
    asm volatile("ldmatrix.sync.aligned.m8n8.x4.shared.b16 {%0,%1,%2,%3}, [%4];" \
        : "=r"((r)[0]), "=r"((r)[1]), "=r"((r)[2]), "=r"((r)[3]) : "r"(addr))

#define MMA16816(c, a, b0, b1) \
    asm volatile("mma.sync.aligned.m16n8k16.row.col.f32.f16.f16.f32 " \
        "{%0,%1,%2,%3}, {%4,%5,%6,%7}, {%8,%9}, {%0,%1,%2,%3};" \
        : "+f"((c)[0]), "+f"((c)[1]), "+f"((c)[2]), "+f"((c)[3]) \
        : "r"((a)[0]), "r"((a)[1]), "r"((a)[2]), "r"((a)[3]), "r"(b0), "r"(b1))

// Fallback per-stage K-block remap (3-product schedule)
__device__ __forceinline__ int a_kblk(int kb) { return (kb < 128) ? (kb & 63) : (kb - 64); }
__device__ __forceinline__ int b_kblk(int kb) { return (kb < 128) ? kb : (kb - 128); }

// ---------------------------------------------------------------- GEMM
__global__ void __launch_bounds__(NTHREADS, 1) gemm_kernel(float* __restrict__ out) {
    extern __shared__ char smem[];
    const uint32_t sbase = smem_u32(smem);
    const int tid = threadIdx.x;
    const int wid = tid >> 5;
    const int lid = tid & 31;

    const int t0 = blockIdx.x * BM;   // m fastest-varying for B-tile L2 reuse
    const int o0 = blockIdx.y * BN;

#if defined(__CUDA_ARCH__) && !defined(__CUDA_ARCH_FEAT_SM103_ALL)
    // ================= HMMA fallback path (compute_103 pass; never runs) =========
    const __half* Ag = g_a + (size_t)t0 * AK;
    const __half* Bg = g_b + (size_t)o0 * AK;

    auto load_stage = [&](int st, int kb) {
        if (kb < KBLKS) {
            const uint32_t abase = sbase + st * STAGE_BYTES;
            const uint32_t bbase = abase + A_ST_BYTES;
            const int ak = a_kblk(kb) * BK;
            const int bk = b_kblk(kb) * BK;
            #pragma unroll
            for (int c = tid; c < (BM + BN) * 8; c += NTHREADS) {
                int row = c >> 3, ch = c & 7;
                if (row < BM)
                    cp_async16(abase + swz(row * 128 + ch * 16),
                               Ag + (size_t)row * AK + ak + ch * 8);
                else
                    cp_async16(bbase + swz((row - BM) * 128 + ch * 16),
                               Bg + (size_t)(row - BM) * AK + bk + ch * 8);
            }
        }
        cp_commit();
    };

    const int warp_m = wid & 1;
    const int warp_n = wid >> 1;
    const int m_off = warp_m * 64;
    const int n_off = warp_n * 32;
    const int lrow = lid & 15;
    const int lc16 = lid >> 4;

    uint32_t preA[4], preB[2];
    #pragma unroll
    for (int mi = 0; mi < 4; mi++)
        preA[mi] = swz((uint32_t)((m_off + mi * 16 + lrow) * 128 + lc16 * 16));
    #pragma unroll
    for (int nj = 0; nj < 2; nj++)
        preB[nj] = swz((uint32_t)((n_off + nj * 16 + lrow) * 128 + lc16 * 16));

    float acc[4][4][4];
    #pragma unroll
    for (int mi = 0; mi < 4; mi++)
        #pragma unroll
        for (int ni = 0; ni < 4; ni++)
            #pragma unroll
            for (int q = 0; q < 4; q++) acc[mi][ni][q] = 0.f;

    load_stage(0, 0);
    load_stage(1, 1);

    for (int kb = 0; kb < KBLKS; kb++) {
        cp_wait<1>();
        __syncthreads();
        load_stage((kb + 2) % NSTAGE, kb + 2);

        const uint32_t sA = sbase + (kb % NSTAGE) * STAGE_BYTES;
        const uint32_t sB = sA + A_ST_BYTES;
        #pragma unroll
        for (int ks = 0; ks < 4; ks++) {
            const uint32_t xk = ks * 32;
            uint32_t a[4][4], b[2][4];
            #pragma unroll
            for (int mi = 0; mi < 4; mi++) LDSM_X4(a[mi], sA + (preA[mi] ^ xk));
            #pragma unroll
            for (int nj = 0; nj < 2; nj++) LDSM_X4(b[nj], sB + (preB[nj] ^ xk));
            #pragma unroll
            for (int mi = 0; mi < 4; mi++)
                #pragma unroll
                for (int ni = 0; ni < 4; ni++)
                    MMA16816(acc[mi][ni], a[mi], b[ni >> 1][ni & 1], b[ni >> 1][2 + (ni & 1)]);
        }
    }

    #pragma unroll
    for (int mi = 0; mi < 4; mi++) {
        const int r0 = t0 + m_off + mi * 16 + (lid >> 2);
        #pragma unroll
        for (int ni = 0; ni < 4; ni++) {
            const int c = o0 + n_off + ni * 8 + ((lid & 3) << 1);
            *reinterpret_cast<float2*>(out + (size_t)r0 * O_DIM + c) =
                make_float2(acc[mi][ni][0], acc[mi][ni][1]);
            *reinterpret_cast<float2*>(out + (size_t)(r0 + 8) * O_DIM + c) =
                make_float2(acc[mi][ni][2], acc[mi][ni][3]);
        }
    }
#else
#if defined(__CUDA_ARCH_FEAT_SM103_ALL)
    // ================= tcgen05 path: fused-K stage, 2-stage ping-pong ============
    // Stage layout (96 KB): [xh 16K | xl 16K | wh0 16K | wh1 16K | wl0 16K | wl1 16K]
    // One K64 block per iter; 3 products (xh*wh, xh*wl, xl*wh) from one stage.
    if (tid == 0) {
        mbar_init(sbase + SMEM_BARS + 0, 1);
        mbar_init(sbase + SMEM_BARS + 8, 1);
    }
    if (wid == 0) {
        asm volatile("tcgen05.alloc.cta_group::1.sync.aligned.shared::cta.b32 [%0], %1;"
                     :: "r"(sbase + SMEM_TMEMP), "r"(256u) : "memory");
        asm volatile("tcgen05.relinquish_alloc_permit.cta_group::1.sync.aligned;");
    }
    __syncthreads();
    uint32_t tmem;
    asm volatile("ld.shared.b32 %0, [%1];" : "=r"(tmem) : "r"(sbase + SMEM_TMEMP));

    // Fused-K stage load: 768 rows x 128 B. Rows 0-127 xh, 128-255 xl,
    // 256-511 wh, 512-767 wl. ALWAYS commits one group.
    auto tc_load = [&](int st, int kb) {
        if (kb < TC_KBLKS) {
            const uint32_t stb = sbase + st * TC_STAGE;
            const int kk = kb * BK;
            #pragma unroll
            for (int j = 0; j < 12; j++) {
                const int c = tid + j * NTHREADS;
                const int r = c >> 3, ch = c & 7;
                const __half* src;
                if (r < 256)
                    src = g_a + (size_t)(t0 + (r & 127)) * AK + ((r >> 7) & 1) * K_DIM + kk + ch * 8;
                else {
                    const int rb = r - 256;
                    src = g_b + (size_t)(o0 + (rb & 255)) * AK + (rb >> 8) * K_DIM + kk + ch * 8;
                }
                cp_async16(stb + swz((uint32_t)(r * 128 + ch * 16)), src);
            }
        }
        cp_commit();
    };

    tc_load(0, 0);
    tc_load(1, 1);

    const uint32_t idesc = (1u << 4) | ((128u / 8) << 17) | ((128u / 16) << 24);
    int ph[2] = {0, 0};

    for (int kb = 0; kb < TC_KBLKS; kb++) {
        const int st = kb & 1;
        cp_wait<1>();
        __syncthreads();

        if (wid == 0 && elect_one()) {
            asm volatile("fence.proxy.async.shared::cta;" ::: "memory");
            const uint32_t stb = sbase + st * TC_STAGE;
            const uint64_t axh = make_desc(stb);
            const uint64_t axl = make_desc(stb + 16384);
            const uint64_t bh0 = make_desc(stb + 32768);
            const uint64_t bh1 = make_desc(stb + 49152);
            const uint64_t bl0 = make_desc(stb + 65536);
            const uint64_t bl1 = make_desc(stb + 81920);
            #pragma unroll
            for (int k = 0; k < 4; k++) {
                const uint32_t acc0 = (kb > 0 || k > 0) ? 1u : 0u;  // first touch: xh*wh only
                mma_f16_ss(tmem,       axh + k * 2, bh0 + k * 2, idesc, acc0);
                mma_f16_ss(tmem + 128, axh + k * 2, bh1 + k * 2, idesc, acc0);
                mma_f16_ss(tmem,       axh + k * 2, bl0 + k * 2, idesc, 1u);
                mma_f16_ss(tmem + 128, axh + k * 2, bl1 + k * 2, idesc, 1u);
                mma_f16_ss(tmem,       axl + k * 2, bh0 + k * 2, idesc, 1u);
                mma_f16_ss(tmem + 128, axl + k * 2, bh1 + k * 2, idesc, 1u);
            }
            tc_commit(sbase + SMEM_BARS + st * 8);
        }

        // Refill this stage once its MMAs finish; prefetch distance 2 gives slack.
        if (kb + 2 < TC_KBLKS) {
            mbar_wait(sbase + SMEM_BARS + st * 8, (uint32_t)ph[st]);
            ph[st] ^= 1;
        }
        tc_load(st, kb + 2);   // loads iff in range; ALWAYS commits
    }

    // Last commit (kb=63, stage 1) covers all prior MMAs.
    mbar_wait(sbase + SMEM_BARS + 8, (uint32_t)ph[1]);
    asm volatile("tcgen05.fence::after_thread_sync;" ::: "memory");

    // Epilogue (R15-identical): 16 warps, 256 TMEM cols
    {
        const int rowsub = (wid & 3) * 32;
        const int cbase0 = (wid >> 2) * 64;
        float* orow = out + (size_t)(t0 + rowsub + lid) * O_DIM + o0 + cbase0;
        #pragma unroll
        for (int cb = 0; cb < 2; cb++) {
            uint32_t r[32];
            TC_LD_X32(r, tmem + cbase0 + cb * 32);
            asm volatile("tcgen05.wait::ld.sync.aligned;" ::: "memory");
            float4* dst = reinterpret_cast<float4*>(orow + cb * 32);
            #pragma unroll
            for (int q = 0; q < 8; q++)
                dst[q] = make_float4(__uint_as_float(r[4 * q + 0]),
                                     __uint_as_float(r[4 * q + 1]),
                                     __uint_as_float(r[4 * q + 2]),
                                     __uint_as_float(r[4 * q + 3]));
        }
    }

    __syncthreads();
    if (tid == 0) {
        mbar_inval(sbase + SMEM_BARS + 0);
        mbar_inval(sbase + SMEM_BARS + 8);
    }
    __syncthreads();
    if (wid == 0) {
        asm volatile("tcgen05.dealloc.cta_group::1.sync.aligned.b32 %0, %1;"
                     :: "r"(tmem), "r"(256u));
    }
#endif
#endif
}

// ---------------------------------------------------------------- launch
extern "C" void kernel_launch(void* const* d_in, const int* in_sizes, int n_in,
                              void* d_out, int out_size) {
    (void)in_sizes; (void)n_in; (void)out_size;
    const float* x = (const float*)d_in[0];
    const float* w = (const float*)d_in[1];
    const float* s = (const float*)d_in[2];
    float* out = (float*)d_out;

    xsplit_kernel<<<2048, 256>>>(x);
    wsplit_kernel<<<2048, 256>>>(w, s);

    cudaFuncSetAttribute(gemm_kernel, cudaFuncAttributeMaxDynamicSharedMemorySize, SMEM_TOTAL);
    dim3 grid(T_DIM / BM, O_DIM / BN);  // (64, 43), m fastest
    gemm_kernel<<<grid, NTHREADS, SMEM_TOTAL>>>(out);
}

// round 17
// speedup vs baseline: 1.9134x; 1.1288x over previous
#include <cuda_runtime.h>
#include <cuda_fp16.h>
#include <cstdint>

// Problem dims
#define T_DIM 8192
#define K_DIM 4096
#define O_DIM 11008
#define QB    64

// Two-term split: A row = [xh(4096) | xl(4096)], B row = [wh(4096) | wl(4096)]
#define AK 8192

// tcgen05 GEMM tiling: 256x256 CTA tile, BK=32 (64B rows, SW64), 3-stage ring
#define BM 256
#define BN 256
#define TC_BK 32
#define TC_KBLKS 128                // 4096 / 32
#define TC_STAGE 65536              // [xh 16K | xl 16K | wh 16K | wl 16K]
#define TC_NST 3
#define NTHREADS 512

// HMMA fallback constants (compute_103 pass only; never runs)
#define NSTAGE 3
#define KBLKS 192
#define BK 64
#define A_ST_BYTES (128 * 128)
#define B_ST_BYTES (256 * 128)
#define STAGE_BYTES (A_ST_BYTES + B_ST_BYTES)  // 49152

#define SMEM_BARS  (TC_NST * TC_STAGE)         // 196608
#define SMEM_TMEMP (SMEM_BARS + TC_NST * 8)
#define SMEM_TOTAL (SMEM_TMEMP + 8)            // 196640

// fp16 scratch (static device arrays: allocation-free contract)
__device__ __align__(16) __half g_a[(size_t)T_DIM * AK];   // [xh | xl]
__device__ __align__(16) __half g_b[(size_t)O_DIM * AK];   // [wh | wl]

// ---------------------------------------------------------------- helpers
__device__ __forceinline__ uint32_t smem_u32(const void* p) {
    uint32_t a;
    asm("{ .reg .u64 t; cvta.to.shared.u64 t, %1; cvt.u32.u64 %0, t; }" : "=r"(a) : "l"(p));
    return a;
}
__device__ __forceinline__ uint32_t swz(uint32_t off)   { return off ^ ((off >> 3) & 0x70); }  // SW128
__device__ __forceinline__ uint32_t swz64(uint32_t off) { return off ^ ((off >> 3) & 0x30); }  // SW64

__device__ __forceinline__ void cp_async16(uint32_t dst, const void* src) {
    asm volatile("cp.async.cg.shared.global [%0], [%1], 16;\n" :: "r"(dst), "l"(src));
}
__device__ __forceinline__ void cp_commit() { asm volatile("cp.async.commit_group;\n" ::: "memory"); }
template <int N>
__device__ __forceinline__ void cp_wait() { asm volatile("cp.async.wait_group %0;\n" :: "n"(N) : "memory"); }

// ---------------------------------------------------------------- prep kernels (proven)
__global__ void __launch_bounds__(256) xsplit_kernel(const float* __restrict__ x) {
    const size_t n4 = (size_t)T_DIM * K_DIM / 4;
    for (size_t v = (size_t)blockIdx.x * blockDim.x + threadIdx.x; v < n4;
         v += (size_t)gridDim.x * blockDim.x) {
        size_t e = v * 4;
        size_t t = e / K_DIM;
        size_t i = e % K_DIM;
        float4 f = reinterpret_cast<const float4*>(x)[v];
        __half h0 = __float2half_rn(f.x), h1 = __float2half_rn(f.y);
        __half h2 = __float2half_rn(f.z), h3 = __float2half_rn(f.w);
        __half l0 = __float2half_rn(f.x - __half2float(h0));
        __half l1 = __float2half_rn(f.y - __half2float(h1));
        __half l2 = __float2half_rn(f.z - __half2float(h2));
        __half l3 = __float2half_rn(f.w - __half2float(h3));
        __half2 hi0 = __halves2half2(h0, h1), hi1 = __halves2half2(h2, h3);
        __half2 lo0 = __halves2half2(l0, l1), lo1 = __halves2half2(l2, l3);
        uint2 uh, ul;
        uh.x = *reinterpret_cast<uint32_t*>(&hi0); uh.y = *reinterpret_cast<uint32_t*>(&hi1);
        ul.x = *reinterpret_cast<uint32_t*>(&lo0); ul.y = *reinterpret_cast<uint32_t*>(&lo1);
        reinterpret_cast<uint2*>(g_a + t * AK + i)[0] = uh;
        reinterpret_cast<uint2*>(g_a + t * AK + K_DIM + i)[0] = ul;
    }
}

__global__ void __launch_bounds__(256) wsplit_kernel(const float* __restrict__ w,
                                                     const float* __restrict__ s) {
    const size_t n4 = (size_t)O_DIM * K_DIM / 4;
    const int SCOLS = K_DIM / QB;  // 64
    for (size_t v = (size_t)blockIdx.x * blockDim.x + threadIdx.x; v < n4;
         v += (size_t)gridDim.x * blockDim.x) {
        size_t e = v * 4;
        size_t o = e / K_DIM;
        size_t i = e % K_DIM;
        float sc = s[(o >> 6) * SCOLS + (i >> 6)];
        float4 f = reinterpret_cast<const float4*>(w)[v];
        float d0 = f.x * sc, d1 = f.y * sc, d2 = f.z * sc, d3 = f.w * sc;
        __half h0 = __float2half_rn(d0), h1 = __float2half_rn(d1);
        __half h2 = __float2half_rn(d2), h3 = __float2half_rn(d3);
        __half l0 = __float2half_rn(d0 - __half2float(h0));
        __half l1 = __float2half_rn(d1 - __half2float(h1));
        __half l2 = __float2half_rn(d2 - __half2float(h2));
        __half l3 = __float2half_rn(d3 - __half2float(h3));
        __half2 hi0 = __halves2half2(h0, h1), hi1 = __halves2half2(h2, h3);
        __half2 lo0 = __halves2half2(l0, l1), lo1 = __halves2half2(l2, l3);
        uint2 uh, ul;
        uh.x = *reinterpret_cast<uint32_t*>(&hi0); uh.y = *reinterpret_cast<uint32_t*>(&hi1);
        ul.x = *reinterpret_cast<uint32_t*>(&lo0); ul.y = *reinterpret_cast<uint32_t*>(&lo1);
        reinterpret_cast<uint2*>(g_b + o * AK + i)[0] = uh;
        reinterpret_cast<uint2*>(g_b + o * AK + K_DIM + i)[0] = ul;
    }
}

// ---------------------------------------------------------------- tcgen05 helpers (feature-gated)
#if !defined(__CUDA_ARCH__) || defined(__CUDA_ARCH_FEAT_SM103_ALL)
__device__ __forceinline__ uint32_t elect_one() {
    uint32_t p;
    asm volatile("{\n\t.reg .pred p;\n\telect.sync _|p, 0xFFFFFFFF;\n\tselp.b32 %0, 1, 0, p;\n\t}" : "=r"(p));
    return p;
}
__device__ __forceinline__ void mbar_init(uint32_t mbar, uint32_t cnt) {
    asm volatile("mbarrier.init.shared.b64 [%0], %1;" :: "r"(mbar), "r"(cnt) : "memory");
}
__device__ __forceinline__ void mbar_inval(uint32_t mbar) {
    asm volatile("mbarrier.inval.shared.b64 [%0];" :: "r"(mbar) : "memory");
}
__device__ __forceinline__ void mbar_wait(uint32_t mbar, uint32_t parity) {
    asm volatile(
        "{\n\t.reg .pred P1;\n\t"
        "WL_%=:\n\t"
        "mbarrier.try_wait.parity.acquire.cta.shared::cta.b64 P1, [%0], %1, 0x989680;\n\t"
        "@P1 bra.uni WD_%=;\n\t"
        "bra.uni WL_%=;\n\t"
        "WD_%=:\n\t}"
        :: "r"(mbar), "r"(parity) : "memory");
}
// SW128 K-major descriptor (fallback-side helper usage)
__device__ __forceinline__ uint64_t make_desc(uint32_t addr) {
    constexpr uint64_t base =
        (uint64_t(2) << 61) | (uint64_t(1) << 46) | (uint64_t(64) << 32) | (uint64_t(1) << 16);
    return base | ((uint64_t)(addr >> 4) & 0x3FFF);
}
// SW64 K-major descriptor: layout=4, version=1, SBO=32 (8 rows x 64B = 512B), LBO=1
__device__ __forceinline__ uint64_t make_desc64(uint32_t addr) {
    constexpr uint64_t base =
        (uint64_t(4) << 61) | (uint64_t(1) << 46) | (uint64_t(32) << 32) | (uint64_t(1) << 16);
    return base | ((uint64_t)(addr >> 4) & 0x3FFF);
}
#if defined(__CUDA_ARCH_FEAT_SM103_ALL)
__device__ __forceinline__ void mma_f16_ss(uint32_t d, uint64_t a, uint64_t b,
                                           uint32_t idesc, uint32_t en) {
    asm volatile(
        "{\n\t.reg .pred p;\n\tsetp.ne.u32 p, %4, 0;\n\t"
        "tcgen05.mma.cta_group::1.kind::f16 [%0], %1, %2, %3, {%5, %5, %5, %5}, p;\n\t}"
        :: "r"(d), "l"(a), "l"(b), "r"(idesc), "r"(en), "r"(0u)
        : "memory");
}
__device__ __forceinline__ void tc_commit(uint32_t mbar) {
    asm volatile(
        "tcgen05.commit.cta_group::1.mbarrier::arrive::one.shared::cluster.b64 [%0];"
        :: "r"(mbar) : "memory");
}
#define TC_LD_X32(r, tmem_addr) \
    asm volatile( \
        "tcgen05.ld.sync.aligned.32x32b.x32.b32 " \
        "{%0, %1, %2, %3, %4, %5, %6, %7, " \
        " %8, %9, %10, %11, %12, %13, %14, %15, " \
        " %16, %17, %18, %19, %20, %21, %22, %23, " \
        " %24, %25, %26, %27, %28, %29, %30, %31}, [%32];" \
        : "=r"((r)[0]),  "=r"((r)[1]),  "=r"((r)[2]),  "=r"((r)[3]), \
          "=r"((r)[4]),  "=r"((r)[5]),  "=r"((r)[6]),  "=r"((r)[7]), \
          "=r"((r)[8]),  "=r"((r)[9]),  "=r"((r)[10]), "=r"((r)[11]), \
          "=r"((r)[12]), "=r"((r)[13]), "=r"((r)[14]), "=r"((r)[15]), \
          "=r"((r)[16]), "=r"((r)[17]), "=r"((r)[18]), "=r"((r)[19]), \
          "=r"((r)[20]), "=r"((r)[21]), "=r"((r)[22]), "=r"((r)[23]), \
          "=r"((r)[24]), "=r"((r)[25]), "=r"((r)[26]), "=r"((r)[27]), \
          "=r"((r)[28]), "=r"((r)[29]), "=r"((r)[30]), "=r"((r)[31]) \
        : "r"(tmem_addr))
#endif
#endif  // tcgen05 helpers

// ---------------------------------------------------------------- HMMA helpers (fallback)
#define LDSM_X4(r, addr) \
    asm volatile("ldmatrix.sync.aligned.m8n8.x4.shared.b16 {%0,%1,%2,%3}, [%4];" \
        : "=r"((r)[0]), "=r"((r)[1]), "=r"((r)[2]), "=r"((r)[3]) : "r"(addr))

#define MMA16816(c, a, b0, b1) \
    asm volatile("mma.sync.aligned.m16n8k16.row.col.f32.f16.f16.f32 " \
        "{%0,%1,%2,%3}, {%4,%5,%6,%7}, {%8,%9}, {%0,%1,%2,%3};" \
        : "+f"((c)[0]), "+f"((c)[1]), "+f"((c)[2]), "+f"((c)[3]) \
        : "r"((a)[0]), "r"((a)[1]), "r"((a)[2]), "r"((a)[3]), "r"(b0), "r"(b1))

__device__ __forceinline__ int a_kblk(int kb) { return (kb < 128) ? (kb & 63) : (kb - 64); }
__device__ __forceinline__ int b_kblk(int kb) { return (kb < 128) ? kb : (kb - 128); }

// ---------------------------------------------------------------- GEMM
__global__ void __launch_bounds__(NTHREADS, 1) gemm_kernel(float* __restrict__ out) {
    extern __shared__ char smem[];
    const uint32_t sbase = smem_u32(smem);
    const int tid = threadIdx.x;
    const int wid = tid >> 5;
    const int lid = tid & 31;

    const int t0 = blockIdx.x * BM;   // m fastest-varying
    const int o0 = blockIdx.y * BN;

#if defined(__CUDA_ARCH__) && !defined(__CUDA_ARCH_FEAT_SM103_ALL)
    // ================= HMMA fallback (compute_103 pass; never runs) ==============
    // Two sequential 128-row passes of the proven 128x256 HMMA body.
    for (int half = 0; half < 2; half++) {
        const int t0h = t0 + half * 128;
        const __half* Ag = g_a + (size_t)t0h * AK;
        const __half* Bg = g_b + (size_t)o0 * AK;

        auto load_fb = [&](int st, int kb) {
            if (kb < KBLKS) {
                const uint32_t abase = sbase + st * STAGE_BYTES;
                const uint32_t bbase = abase + A_ST_BYTES;
                const int ak = a_kblk(kb) * BK;
                const int bk = b_kblk(kb) * BK;
                #pragma unroll
                for (int c = tid; c < (128 + 256) * 8; c += NTHREADS) {
                    int row = c >> 3, ch = c & 7;
                    if (row < 128)
                        cp_async16(abase + swz(row * 128 + ch * 16),
                                   Ag + (size_t)row * AK + ak + ch * 8);
                    else
                        cp_async16(bbase + swz((row - 128) * 128 + ch * 16),
                                   Bg + (size_t)(row - 128) * AK + bk + ch * 8);
                }
            }
            cp_commit();
        };

        const int warp_m = wid & 1;
        const int warp_n = wid >> 1;
        const int m_off = warp_m * 64;
        const int n_off = warp_n * 32;
        const int lrow = lid & 15;
        const int lc16 = lid >> 4;

        uint32_t preA[4], preB[2];
        #pragma unroll
        for (int mi = 0; mi < 4; mi++)
            preA[mi] = swz((uint32_t)((m_off + mi * 16 + lrow) * 128 + lc16 * 16));
        #pragma unroll
        for (int nj = 0; nj < 2; nj++)
            preB[nj] = swz((uint32_t)((n_off + nj * 16 + lrow) * 128 + lc16 * 16));

        float acc[4][4][4];
        #pragma unroll
        for (int mi = 0; mi < 4; mi++)
            #pragma unroll
            for (int ni = 0; ni < 4; ni++)
                #pragma unroll
                for (int q = 0; q < 4; q++) acc[mi][ni][q] = 0.f;

        load_fb(0, 0);
        load_fb(1, 1);

        for (int kb = 0; kb < KBLKS; kb++) {
            cp_wait<1>();
            __syncthreads();
            load_fb((kb + 2) % NSTAGE, kb + 2);

            const uint32_t sA = sbase + (kb % NSTAGE) * STAGE_BYTES;
            const uint32_t sB = sA + A_ST_BYTES;
            #pragma unroll
            for (int ks = 0; ks < 4; ks++) {
                const uint32_t xk = ks * 32;
                uint32_t a[4][4], b[2][4];
                #pragma unroll
                for (int mi = 0; mi < 4; mi++) LDSM_X4(a[mi], sA + (preA[mi] ^ xk));
                #pragma unroll
                for (int nj = 0; nj < 2; nj++) LDSM_X4(b[nj], sB + (preB[nj] ^ xk));
                #pragma unroll
                for (int mi = 0; mi < 4; mi++)
                    #pragma unroll
                    for (int ni = 0; ni < 4; ni++)
                        MMA16816(acc[mi][ni], a[mi], b[ni >> 1][ni & 1], b[ni >> 1][2 + (ni & 1)]);
            }
        }
        cp_wait<0>();
        __syncthreads();

        #pragma unroll
        for (int mi = 0; mi < 4; mi++) {
            const int r0 = t0h + m_off + mi * 16 + (lid >> 2);
            #pragma unroll
            for (int ni = 0; ni < 4; ni++) {
                const int c = o0 + n_off + ni * 8 + ((lid & 3) << 1);
                *reinterpret_cast<float2*>(out + (size_t)r0 * O_DIM + c) =
                    make_float2(acc[mi][ni][0], acc[mi][ni][1]);
                *reinterpret_cast<float2*>(out + (size_t)(r0 + 8) * O_DIM + c) =
                    make_float2(acc[mi][ni][2], acc[mi][ni][3]);
            }
        }
        __syncthreads();
    }
#else
#if defined(__CUDA_ARCH_FEAT_SM103_ALL)
    // ======= tcgen05 path: 256x256 tile, BK=32 SW64 stages, 3-stage ring =========
    // Stage (64 KB): [xh 16K | xl 16K | wh 16K | wl 16K], 64B rows, SW64 swizzle.
    if (tid == 0) {
        #pragma unroll
        for (int st = 0; st < TC_NST; st++) mbar_init(sbase + SMEM_BARS + st * 8, 1);
    }
    if (wid == 0) {
        asm volatile("tcgen05.alloc.cta_group::1.sync.aligned.shared::cta.b32 [%0], %1;"
                     :: "r"(sbase + SMEM_TMEMP), "r"(512u) : "memory");
        asm volatile("tcgen05.relinquish_alloc_permit.cta_group::1.sync.aligned;");
    }
    __syncthreads();
    uint32_t tmem;
    asm volatile("ld.shared.b32 %0, [%1];" : "=r"(tmem) : "r"(sbase + SMEM_TMEMP));

    // Stage load: 1024 rows x 64 B = 4096 x 16B chunks = 512 thr x 8.
    // Rows 0-255 xh, 256-511 xl, 512-767 wh, 768-1023 wl. ALWAYS commits.
    auto tc_load = [&](int st, int kb) {
        if (kb < TC_KBLKS) {
            const uint32_t stb = sbase + st * TC_STAGE;
            const int kk = kb * TC_BK;
            #pragma unroll
            for (int j = 0; j < 8; j++) {
                const int c = tid + j * NTHREADS;
                const int r = c >> 2, ch = c & 3;
                const __half* src;
                if (r < 512)
                    src = g_a + (size_t)(t0 + (r & 255)) * AK + ((r >> 8) & 1) * K_DIM + kk + ch * 8;
                else {
                    const int rb = r - 512;
                    src = g_b + (size_t)(o0 + (rb & 255)) * AK + (rb >> 8) * K_DIM + kk + ch * 8;
                }
                cp_async16(stb + swz64((uint32_t)(r * 64 + ch * 16)), src);
            }
        }
        cp_commit();
    };

    tc_load(0, 0);
    tc_load(1, 1);

    const uint32_t idesc = (1u << 4) | ((128u / 8) << 17) | ((128u / 16) << 24);
    int ph[TC_NST] = {0, 0, 0};

    for (int kb = 0; kb < TC_KBLKS; kb++) {
        const int st = kb % TC_NST;
        cp_wait<1>();
        __syncthreads();

        if (wid == 0 && elect_one()) {
            asm volatile("fence.proxy.async.shared::cta;" ::: "memory");
            const uint32_t stb = sbase + st * TC_STAGE;
            uint64_t axh[2], axl[2], bwh[2], bwl[2];
            #pragma unroll
            for (int h = 0; h < 2; h++) {
                axh[h] = make_desc64(stb + h * 8192);
                axl[h] = make_desc64(stb + 16384 + h * 8192);
                bwh[h] = make_desc64(stb + 32768 + h * 8192);
                bwl[h] = make_desc64(stb + 49152 + h * 8192);
            }
            #pragma unroll
            for (int k = 0; k < 2; k++) {      // 2 x K16 steps per K32 stage
                const uint32_t acc0 = (kb > 0 || k > 0) ? 1u : 0u;
                #pragma unroll
                for (int dt = 0; dt < 4; dt++) {
                    const int mi = dt >> 1, ni = dt & 1;
                    const uint32_t d = tmem + dt * 128;
                    mma_f16_ss(d, axh[mi] + k * 2, bwh[ni] + k * 2, idesc, acc0);
                    mma_f16_ss(d, axh[mi] + k * 2, bwl[ni] + k * 2, idesc, 1u);
                    mma_f16_ss(d, axl[mi] + k * 2, bwh[ni] + k * 2, idesc, 1u);
                }
            }
            tc_commit(sbase + SMEM_BARS + st * 8);
        }

        // Refill stage used by MMA(kb-1): (kb+2)%3 == (kb-1)%3; TRYWAIT fast-path.
        {
            const int nkb = kb + 2;
            const int pst = nkb % TC_NST;
            if (nkb < TC_KBLKS && kb >= 1) {
                mbar_wait(sbase + SMEM_BARS + pst * 8, (uint32_t)ph[pst]);
                ph[pst] ^= 1;
            }
            tc_load(pst, nkb);   // loads iff in range; ALWAYS commits
        }
    }

    // Final commit (kb = TC_KBLKS-1) covers all prior MMAs (tensor-pipe ordered).
    {
        const int lst = (TC_KBLKS - 1) % TC_NST;
        mbar_wait(sbase + SMEM_BARS + lst * 8, (uint32_t)ph[lst]);
    }
    asm volatile("tcgen05.fence::after_thread_sync;" ::: "memory");

    // Epilogue: 16 warps; warp -> (D quadrant = wid>>2, subpartition = wid&3).
    // Quadrants at TMEM cols 0/128/256/384 = (m0,n0),(m0,n1),(m1,n0),(m1,n1).
    {
        const int sub = wid & 3;
        const int dt = wid >> 2;
        const int mi = dt >> 1, ni = dt & 1;
        float* orow = out + (size_t)(t0 + mi * 128 + sub * 32 + lid) * O_DIM
                      + o0 + ni * 128;
        #pragma unroll
        for (int cb = 0; cb < 4; cb++) {
            uint32_t r[32];
            TC_LD_X32(r, tmem + dt * 128 + cb * 32);
            asm volatile("tcgen05.wait::ld.sync.aligned;" ::: "memory");
            float4* dst = reinterpret_cast<float4*>(orow + cb * 32);
            #pragma unroll
            for (int q = 0; q < 8; q++)
                dst[q] = make_float4(__uint_as_float(r[4 * q + 0]),
                                     __uint_as_float(r[4 * q + 1]),
                                     __uint_as_float(r[4 * q + 2]),
                                     __uint_as_float(r[4 * q + 3]));
        }
    }

    __syncthreads();
    if (tid == 0) {
        #pragma unroll
        for (int st = 0; st < TC_NST; st++) mbar_inval(sbase + SMEM_BARS + st * 8);
    }
    __syncthreads();
    if (wid == 0) {
        asm volatile("tcgen05.dealloc.cta_group::1.sync.aligned.b32 %0, %1;"
                     :: "r"(tmem), "r"(512u));
    }
#endif
#endif
}

// ---------------------------------------------------------------- launch
extern "C" void kernel_launch(void* const* d_in, const int* in_sizes, int n_in,
                              void* d_out, int out_size) {
    (void)in_sizes; (void)n_in; (void)out_size;
    const float* x = (const float*)d_in[0];
    const float* w = (const float*)d_in[1];
    const float* s = (const float*)d_in[2];
    float* out = (float*)d_out;

    xsplit_kernel<<<2048, 256>>>(x);
    wsplit_kernel<<<2048, 256>>>(w, s);

    cudaFuncSetAttribute(gemm_kernel, cudaFuncAttributeMaxDynamicSharedMemorySize, SMEM_TOTAL);
    dim3 grid(T_DIM / BM, O_DIM / BN);  // (32, 43), m fastest
    gemm_kernel<<<grid, NTHREADS, SMEM_TOTAL>>>(out);
}